// round 13
// baseline (speedup 1.0000x reference)
#include <cuda_runtime.h>
#include <cuda_bf16.h>
#include <math.h>
#include <cstdint>

// Problem constants
#define Bb 4
#define Tt 1024
#define Cc 1024
#define Hh 16
#define HKV 4
#define Dd 64
#define ROWS (Bb*Tt)          // 4096 tokens
#define QDIM (Hh*Dd)          // 1024
#define KVDIM (HKV*Dd)        // 256
#define GATE_CH 12

#define XN  (ROWS * Cc)
#define WQN (QDIM * Cc)
#define WKN (KVDIM * Cc)
#define WON (Cc * Cc)

// Scratch (no cudaMalloc allowed)
__device__ float g_Q[ROWS * QDIM];    // 16 MB
__device__ float g_K[ROWS * KVDIM];   // 4 MB
__device__ float g_V[ROWS * KVDIM];   // 4 MB
__device__ float g_Y[ROWS * QDIM];    // 16 MB
__device__ float g_Xr[XN];            // 16 MB  tf32-rounded x
__device__ float g_Wqr[WQN];          // 4 MB
__device__ float g_Wkr[WKN];          // 1 MB
__device__ float g_Wvr[WKN];          // 1 MB
__device__ float g_Wor[WON];          // 4 MB

__device__ __forceinline__ float tf32r(float x) {
    float y;
    asm("cvt.rna.tf32.f32 %0, %1;" : "=f"(y) : "f"(x));
    return y;
}

__device__ __forceinline__ void mma_tf32(float* d,
                                         const uint32_t* a, const uint32_t* b) {
    asm volatile(
        "mma.sync.aligned.m16n8k8.row.col.f32.tf32.tf32.f32 "
        "{%0,%1,%2,%3}, {%4,%5,%6,%7}, {%8,%9}, {%0,%1,%2,%3};"
        : "+f"(d[0]), "+f"(d[1]), "+f"(d[2]), "+f"(d[3])
        : "r"(a[0]), "r"(a[1]), "r"(a[2]), "r"(a[3]),
          "r"(b[0]), "r"(b[1]));
}

__device__ __forceinline__ void mma_tf32f(float* d,
                                          const uint32_t* a, float b0, float b1) {
    uint32_t b[2] = { __float_as_uint(b0), __float_as_uint(b1) };
    mma_tf32(d, a, b);
}

__device__ __forceinline__ void cpa16(float* s, const float* g) {
    uint32_t sa = (uint32_t)__cvta_generic_to_shared(s);
    asm volatile("cp.async.cg.shared.global [%0], [%1], 16;"
                 :: "r"(sa), "l"(g) : "memory");
}

// ---------------------------------------------------------------------------
// Pre-round pass: tf32-round x and all GEMM weights once (contiguous copies).
// ---------------------------------------------------------------------------
#define RND_TOTAL4 ((XN + WQN + 2 * WKN + WON) / 4)

__global__ __launch_bounds__(256) void round_pass(
    const float* __restrict__ x,
    const float* __restrict__ Wq, const float* __restrict__ Wk,
    const float* __restrict__ Wv, const float* __restrict__ Wo)
{
    int id = blockIdx.x * 256 + threadIdx.x;
    if (id >= RND_TOTAL4) return;
    int e = id * 4;
    const float* src;
    float* dst;
    if (e < XN)                { src = x  + e;         dst = g_Xr  + e; }
    else if ((e -= XN) < WQN)  { src = Wq + e;         dst = g_Wqr + e; }
    else if ((e -= WQN) < WKN) { src = Wk + e;         dst = g_Wkr + e; }
    else if ((e -= WKN) < WKN) { src = Wv + e;         dst = g_Wvr + e; }
    else                       { src = Wo + (e - WKN); dst = g_Wor + (e - WKN); }
    float4 v = *(const float4*)src;
    v.x = tf32r(v.x); v.y = tf32r(v.y); v.z = tf32r(v.z); v.w = tf32r(v.w);
    *(float4*)dst = v;
}

// ---------------------------------------------------------------------------
// tf32 mma.sync GEMM core (R7 layout):  C_tile = A[128,K] * B[128,K]^T
// ---------------------------------------------------------------------------
#define LDS_S 36
#define STG (128 * LDS_S)

__device__ __forceinline__ void gemm_body(
    const float* __restrict__ Ab, const float* __restrict__ Bp,
    float* __restrict__ Crow0, int N, int K, float* __restrict__ sm)
{
    float* smA = sm;
    float* smB = sm + 2 * STG;

    const int tid = threadIdx.x;
    const int wid = tid >> 5;
    const int lane = tid & 31;
    const int warp_m = wid & 3;
    const int warp_n = wid >> 2;
    const int group = lane >> 2;
    const int kq = lane & 3;

    float acc[2][8][4];
#pragma unroll
    for (int mt = 0; mt < 2; mt++)
#pragma unroll
        for (int nt = 0; nt < 8; nt++)
#pragma unroll
            for (int c = 0; c < 4; c++) acc[mt][nt][c] = 0.f;

    const int nk = K >> 5;

#pragma unroll
    for (int t = 0; t < 4; t++) {
        int idx = tid + t * 256;
        int row = idx >> 3;
        int c4  = (idx & 7) << 2;
        cpa16(smA + row * LDS_S + c4, Ab + (size_t)row * K + c4);
        cpa16(smB + row * LDS_S + c4, Bp + (size_t)row * K + c4);
    }
    asm volatile("cp.async.commit_group;" ::: "memory");

    for (int kc = 0; kc < nk; kc++) {
        asm volatile("cp.async.wait_group 0;" ::: "memory");
        __syncthreads();

        if (kc + 1 < nk) {
            float* dA = smA + ((kc + 1) & 1) * STG;
            float* dB = smB + ((kc + 1) & 1) * STG;
            const int koff = (kc + 1) << 5;
#pragma unroll
            for (int t = 0; t < 4; t++) {
                int idx = tid + t * 256;
                int row = idx >> 3;
                int c4  = (idx & 7) << 2;
                cpa16(dA + row * LDS_S + c4, Ab + (size_t)row * K + koff + c4);
                cpa16(dB + row * LDS_S + c4, Bp + (size_t)row * K + koff + c4);
            }
            asm volatile("cp.async.commit_group;" ::: "memory");
        }

        const uint32_t* As = (const uint32_t*)(smA + (kc & 1) * STG);
        const uint32_t* Bs = (const uint32_t*)(smB + (kc & 1) * STG);
#pragma unroll
        for (int ks = 0; ks < 4; ks++) {
            const int k0 = ks * 8;
            uint32_t af[2][4];
#pragma unroll
            for (int mt = 0; mt < 2; mt++) {
                const uint32_t* ar = As + (warp_m * 32 + mt * 16 + group) * LDS_S + k0 + kq;
                af[mt][0] = ar[0];
                af[mt][1] = ar[8 * LDS_S];
                af[mt][2] = ar[4];
                af[mt][3] = ar[8 * LDS_S + 4];
            }
            uint32_t bf[8][2];
#pragma unroll
            for (int nt = 0; nt < 8; nt++) {
                const uint32_t* br = Bs + (warp_n * 64 + nt * 8 + group) * LDS_S + k0 + kq;
                bf[nt][0] = br[0];
                bf[nt][1] = br[4];
            }
#pragma unroll
            for (int mt = 0; mt < 2; mt++)
#pragma unroll
                for (int nt = 0; nt < 8; nt++)
                    mma_tf32(acc[mt][nt], af[mt], bf[nt]);
        }
    }

#pragma unroll
    for (int mt = 0; mt < 2; mt++) {
        int r = warp_m * 32 + mt * 16 + group;
#pragma unroll
        for (int nt = 0; nt < 8; nt++) {
            int cn = warp_n * 64 + nt * 8 + 2 * kq;
            *(float2*)(Crow0 + (size_t)r * N + cn) =
                make_float2(acc[mt][nt][0], acc[mt][nt][1]);
            *(float2*)(Crow0 + (size_t)(r + 8) * N + cn) =
                make_float2(acc[mt][nt][2], acc[mt][nt][3]);
        }
    }
}

// Merged QKV projection: grid.x 0..7 -> Q, 8..9 -> K, 10..11 -> V
__global__ __launch_bounds__(256, 2) void gemm_qkv(
    float* __restrict__ Qo, float* __restrict__ Ko, float* __restrict__ Vo)
{
    extern __shared__ float sm[];
    const int bx = blockIdx.x;
    const float* Bp;
    float* Cp;
    int N, nb;
    if (bx < 8)       { Bp = g_Wqr; Cp = Qo; N = QDIM;  nb = bx; }
    else if (bx < 10) { Bp = g_Wkr; Cp = Ko; N = KVDIM; nb = bx - 8; }
    else              { Bp = g_Wvr; Cp = Vo; N = KVDIM; nb = bx - 10; }
    gemm_body(g_Xr + (size_t)blockIdx.y * 128 * Cc,
              Bp + (size_t)nb * 128 * Cc,
              Cp + (size_t)blockIdx.y * 128 * N + nb * 128, N, Cc, sm);
}

__global__ __launch_bounds__(256, 2) void gemm_tc(
    const float* __restrict__ A, const float* __restrict__ B,
    float* __restrict__ C, int N, int K)
{
    extern __shared__ float sm[];
    gemm_body(A + (size_t)blockIdx.y * 128 * K,
              B + (size_t)blockIdx.x * 128 * K,
              C + (size_t)blockIdx.y * 128 * N + blockIdx.x * 128, N, K, sm);
}

// ---------------------------------------------------------------------------
// Postproc: per-token gate+V update, RoPE + RMS-norm on Q and K.
// ---------------------------------------------------------------------------
__global__ __launch_bounds__(256) void postproc(
    const float* __restrict__ x, const float* __restrict__ ve,
    const float* __restrict__ cosb, const float* __restrict__ sinb,
    const float* __restrict__ Wg)
{
    const int row = blockIdx.x;
    const int t = row & (Tt - 1);
    const int warp = threadIdx.x >> 5;
    const int lane = threadIdx.x & 31;

    if (warp < HKV) {
        float p = 0.f;
        if (lane < GATE_CH)
            p = x[(size_t)row * Cc + lane] * Wg[warp * GATE_CH + lane];
#pragma unroll
        for (int o = 16; o > 0; o >>= 1)
            p += __shfl_xor_sync(0xffffffffu, p, o);
        float gate = 3.f / (1.f + __expf(-p));
        size_t base = (size_t)row * KVDIM + warp * Dd;
        g_V[base + lane]      += gate * ve[base + lane];
        g_V[base + 32 + lane] += gate * ve[base + 32 + lane];
    }

    const float cv = cosb[t * 32 + lane];
    const float sv = sinb[t * 32 + lane];
    for (int tsk = warp; tsk < Hh + HKV; tsk += 8) {
        float* ptr = (tsk < Hh)
            ? (g_Q + (size_t)row * QDIM + tsk * Dd)
            : (g_K + (size_t)row * KVDIM + (tsk - Hh) * Dd);
        float x1 = ptr[lane];
        float x2 = ptr[lane + 32];
        float y1 = x1 * cv + x2 * sv;
        float y2 = x2 * cv - x1 * sv;
        float ss = y1 * y1 + y2 * y2;
#pragma unroll
        for (int o = 16; o > 0; o >>= 1)
            ss += __shfl_xor_sync(0xffffffffu, ss, o);
        float sc = 1.2f * rsqrtf(ss * (1.0f / Dd) + 1.1920929e-7f);
        ptr[lane]      = y1 * sc;
        ptr[lane + 32] = y2 * sc;
    }
}

// ---------------------------------------------------------------------------
// mma.sync flash attention, M=128 (32 queries x 4 GQA heads per CTA).
// Smem layouts use in-kernel permutations so ALL fragment loads are LDS.128:
//   Ks[key][pd(d)]  pd(d) = (d&~31) + ((d&3)<<3) + ((d&31)>>2)
//   Vs[key][qv(d)]  qv(d) = (d&~31) + ((d&7)<<2) + ((d&31)>>3)
//   Ss[row][pd(j)]  (same pd on the key axis)
// Store and load use the same map -> bit-exact vs previous rounds.
// Fully-masked 8-key blocks are skipped via [ntlo,nthi) (exact-0 contributions).
// ---------------------------------------------------------------------------
#define SST 68   // smem row stride (floats)
#define QT 32    // queries per CTA

__global__ __launch_bounds__(256, 2) void attn_mma(const int* __restrict__ wptr)
{
    extern __shared__ float dsm[];
    float* Ss = dsm;                        // [128][SST]
    float* Ks = dsm + 128 * SST;            // [64][SST]
    float* Vs = Ks + 64 * SST;              // [64][SST]

    const int qt = blockIdx.x, g = blockIdx.y, b = blockIdx.z;
    const int tid = threadIdx.x;
    const int wid = tid >> 5;
    const int lane = tid & 31;
    const int group = lane >> 2;
    const int kq = lane & 3;
    const int head = g * 4 + (wid >> 1);
    const int q0 = qt * QT;
    const int qloc0 = (wid & 1) * 16;

    // Q fragments (registers), tf32-rounded
    uint32_t qf[8][4];
    {
        const float* Qb = g_Q + ((size_t)(b * Tt + q0 + qloc0)) * QDIM + head * Dd;
        int r0 = group;
#pragma unroll
        for (int ks = 0; ks < 8; ks++) {
            int k0 = ks * 8 + kq;
            qf[ks][0] = __float_as_uint(tf32r(Qb[(size_t)r0 * QDIM + k0]));
            qf[ks][1] = __float_as_uint(tf32r(Qb[(size_t)(r0 + 8) * QDIM + k0]));
            qf[ks][2] = __float_as_uint(tf32r(Qb[(size_t)r0 * QDIM + k0 + 4]));
            qf[ks][3] = __float_as_uint(tf32r(Qb[(size_t)(r0 + 8) * QDIM + k0 + 4]));
        }
    }

    float oacc[8][4];
#pragma unroll
    for (int nt = 0; nt < 8; nt++)
#pragma unroll
        for (int c = 0; c < 4; c++) oacc[nt][c] = 0.f;

    float m0 = -1e30f, m1 = -1e30f, l0 = 0.f, l1 = 0.f;

    const int w = wptr[0];
    int jmin = q0 - w; if (jmin < 0) jmin = 0;

    for (int c0 = (jmin >> 6) << 6; c0 <= q0; c0 += 64) {
        // live 8-key block range [ntlo, nthi)
        int dlo = q0 - w - c0;
        int ntlo = dlo > 0 ? (dlo >> 3) : 0;
        int nthi = ((q0 + 31 - c0) >> 3) + 1;
        if (nthi > 8) nthi = 8;
        const int klo = ntlo * 8, khi = nthi * 8;

        // load K,V chunk into PERMUTED smem (tf32-rounded)
#pragma unroll
        for (int t = 0; t < 4; t++) {
            int idx = tid + t * 256;
            int key = idx >> 4;
            int d4  = (idx & 15) << 2;
            if (key >= klo && key < khi) {
                size_t src = ((size_t)(b * Tt + c0 + key)) * KVDIM + g * Dd + d4;
                float4 kv = *(const float4*)&g_K[src];
                float4 vv = *(const float4*)&g_V[src];
                // K: pd(d4+i) = (d4&~31) + ((d4&31)>>2) + i*8
                float* kd = &Ks[key * SST + (d4 & ~31) + ((d4 & 31) >> 2)];
                kd[0]  = tf32r(kv.x); kd[8]  = tf32r(kv.y);
                kd[16] = tf32r(kv.z); kd[24] = tf32r(kv.w);
                // V: qv(d4+i) = (d4&~31) + ((d4&31)>>3) + ((d4&7)+i)*4
                float* vd = &Vs[key * SST + (d4 & ~31) + ((d4 & 31) >> 3) + (d4 & 7) * 4];
                vd[0]  = tf32r(vv.x); vd[4]  = tf32r(vv.y);
                vd[8]  = tf32r(vv.z); vd[12] = tf32r(vv.w);
            }
        }
        __syncthreads();

        // scores: S = Q * K^T   (K fragments via LDS.128 from permuted Ks)
        float sacc[8][4];
#pragma unroll
        for (int nt = 0; nt < 8; nt++)
#pragma unroll
            for (int c = 0; c < 4; c++) sacc[nt][c] = 0.f;

#pragma unroll
        for (int nt = 0; nt < 8; nt++) {
            if (nt < ntlo || nt >= nthi) continue;
            const float* kr = &Ks[(nt * 8 + group) * SST + kq * 8];
            float karr[16];
            *(float4*)&karr[0]  = *(const float4*)kr;
            *(float4*)&karr[4]  = *(const float4*)(kr + 4);
            *(float4*)&karr[8]  = *(const float4*)(kr + 32);
            *(float4*)&karr[12] = *(const float4*)(kr + 36);
#pragma unroll
            for (int ks = 0; ks < 8; ks++)
                mma_tf32f(sacc[nt], qf[ks], karr[2 * ks], karr[2 * ks + 1]);
        }

        // mask + scale + online softmax; store P to permuted Ss
        {
            const int i0 = q0 + qloc0 + group;
            const int i1 = i0 + 8;
            float cmax0 = -1e30f, cmax1 = -1e30f;
#pragma unroll
            for (int nt = 0; nt < 8; nt++) {
                if (nt < ntlo || nt >= nthi) continue;
                int jg = c0 + nt * 8 + 2 * kq;
                float s;
                s = (jg     <= i0 && (i0 - jg)     <= w) ? sacc[nt][0] * 0.125f : -1e30f;
                sacc[nt][0] = s; cmax0 = fmaxf(cmax0, s);
                s = (jg + 1 <= i0 && (i0 - jg - 1) <= w) ? sacc[nt][1] * 0.125f : -1e30f;
                sacc[nt][1] = s; cmax0 = fmaxf(cmax0, s);
                s = (jg     <= i1 && (i1 - jg)     <= w) ? sacc[nt][2] * 0.125f : -1e30f;
                sacc[nt][2] = s; cmax1 = fmaxf(cmax1, s);
                s = (jg + 1 <= i1 && (i1 - jg - 1) <= w) ? sacc[nt][3] * 0.125f : -1e30f;
                sacc[nt][3] = s; cmax1 = fmaxf(cmax1, s);
            }
            cmax0 = fmaxf(cmax0, __shfl_xor_sync(0xffffffffu, cmax0, 1));
            cmax0 = fmaxf(cmax0, __shfl_xor_sync(0xffffffffu, cmax0, 2));
            cmax1 = fmaxf(cmax1, __shfl_xor_sync(0xffffffffu, cmax1, 1));
            cmax1 = fmaxf(cmax1, __shfl_xor_sync(0xffffffffu, cmax1, 2));

            float mn0 = fmaxf(m0, cmax0);
            float mn1 = fmaxf(m1, cmax1);
            float r0 = __expf(m0 - mn0);
            float r1 = __expf(m1 - mn1);
            m0 = mn0; m1 = mn1;
            l0 *= r0; l1 *= r1;
#pragma unroll
            for (int nt = 0; nt < 8; nt++) {
                oacc[nt][0] *= r0; oacc[nt][1] *= r0;
                oacc[nt][2] *= r1; oacc[nt][3] *= r1;
            }
            const int prow0 = wid * 16 + group;
            // ps(j=nt*8+2kq) = (nt&4)*8 + (kq&1)*16 + 2*(nt&3) + (kq>>1); j+1 -> +8
            const int psb = ((kq & 1) << 4) + (kq >> 1);
#pragma unroll
            for (int nt = 0; nt < 8; nt++) {
                if (nt < ntlo || nt >= nthi) continue;
                float p0 = tf32r(__expf(sacc[nt][0] - mn0));
                float p1 = tf32r(__expf(sacc[nt][1] - mn0));
                float p2 = tf32r(__expf(sacc[nt][2] - mn1));
                float p3 = tf32r(__expf(sacc[nt][3] - mn1));
                l0 += p0 + p1;
                l1 += p2 + p3;
                int ps = ((nt & 4) << 3) + psb + ((nt & 3) << 1);
                float* s0 = &Ss[prow0 * SST + ps];
                float* s1 = &Ss[(prow0 + 8) * SST + ps];
                s0[0] = p0; s0[8] = p1;
                s1[0] = p2; s1[8] = p3;
            }
        }
        __syncwarp();

        // PV: O += P * V   (P A-fragments + V B-fragments via LDS.128)
        {
            const int prow0 = wid * 16 + group;
            const float* pr0 = &Ss[prow0 * SST + kq * 8];
            const float* pr1 = pr0 + 8 * SST;
            float p0arr[16], p1arr[16];
            *(float4*)&p0arr[0]  = *(const float4*)pr0;
            *(float4*)&p0arr[4]  = *(const float4*)(pr0 + 4);
            *(float4*)&p0arr[8]  = *(const float4*)(pr0 + 32);
            *(float4*)&p0arr[12] = *(const float4*)(pr0 + 36);
            *(float4*)&p1arr[0]  = *(const float4*)pr1;
            *(float4*)&p1arr[4]  = *(const float4*)(pr1 + 4);
            *(float4*)&p1arr[8]  = *(const float4*)(pr1 + 32);
            *(float4*)&p1arr[12] = *(const float4*)(pr1 + 36);
#pragma unroll
            for (int ks = 0; ks < 8; ks++) {
                if (ks < ntlo || ks >= nthi) continue;
                const float* vr0 = &Vs[(ks * 8 + kq) * SST + group * 4];
                const float* vr1 = &Vs[(ks * 8 + kq + 4) * SST + group * 4];
                float v0arr[8], v1arr[8];
                *(float4*)&v0arr[0] = *(const float4*)vr0;
                *(float4*)&v0arr[4] = *(const float4*)(vr0 + 32);
                *(float4*)&v1arr[0] = *(const float4*)vr1;
                *(float4*)&v1arr[4] = *(const float4*)(vr1 + 32);
                uint32_t af[4];
                af[0] = __float_as_uint(p0arr[2 * ks]);
                af[1] = __float_as_uint(p1arr[2 * ks]);
                af[2] = __float_as_uint(p0arr[2 * ks + 1]);
                af[3] = __float_as_uint(p1arr[2 * ks + 1]);
#pragma unroll
                for (int nt = 0; nt < 8; nt++)
                    mma_tf32f(oacc[nt], af, v0arr[nt], v1arr[nt]);
            }
        }
        __syncthreads();
    }

    // finalize: store tf32-rounded Y
    {
        l0 += __shfl_xor_sync(0xffffffffu, l0, 1);
        l0 += __shfl_xor_sync(0xffffffffu, l0, 2);
        l1 += __shfl_xor_sync(0xffffffffu, l1, 1);
        l1 += __shfl_xor_sync(0xffffffffu, l1, 2);
        float inv0 = 1.f / l0, inv1 = 1.f / l1;
        int r0 = q0 + qloc0 + group;
        float* Y0 = g_Y + ((size_t)(b * Tt + r0)) * QDIM + head * Dd;
        float* Y1 = g_Y + ((size_t)(b * Tt + r0 + 8)) * QDIM + head * Dd;
#pragma unroll
        for (int nt = 0; nt < 8; nt++) {
            int cn = nt * 8 + 2 * kq;
            *(float2*)(Y0 + cn) = make_float2(tf32r(oacc[nt][0] * inv0),
                                              tf32r(oacc[nt][1] * inv0));
            *(float2*)(Y1 + cn) = make_float2(tf32r(oacc[nt][2] * inv1),
                                              tf32r(oacc[nt][3] * inv1));
        }
    }
}

// ---------------------------------------------------------------------------
extern "C" void kernel_launch(void* const* d_in, const int* in_sizes, int n_in,
                              void* d_out, int out_size)
{
    const float* x    = (const float*)d_in[0];
    const float* ve   = (const float*)d_in[1];
    const float* cosb = (const float*)d_in[2];
    const float* sinb = (const float*)d_in[3];
    const float* Wq   = (const float*)d_in[4];
    const float* Wk   = (const float*)d_in[5];
    const float* Wv   = (const float*)d_in[6];
    const float* Wo   = (const float*)d_in[7];
    const float* Wg   = (const float*)d_in[8];
    const int*   win  = (const int*)d_in[9];

    float* out = (float*)d_out;

    float* Qp; cudaGetSymbolAddress((void**)&Qp, g_Q);
    float* Kp; cudaGetSymbolAddress((void**)&Kp, g_K);
    float* Vp; cudaGetSymbolAddress((void**)&Vp, g_V);
    float* Yp; cudaGetSymbolAddress((void**)&Yp, g_Y);
    float* Wor; cudaGetSymbolAddress((void**)&Wor, g_Wor);

    const int GEMM_SMEM = 4 * STG * 4;            // 73728 bytes
    const int ATTN_SMEM = (128 + 128) * SST * 4;  // 69632 bytes
    cudaFuncSetAttribute(gemm_qkv,
        cudaFuncAttributeMaxDynamicSharedMemorySize, GEMM_SMEM);
    cudaFuncSetAttribute(gemm_tc,
        cudaFuncAttributeMaxDynamicSharedMemorySize, GEMM_SMEM);
    cudaFuncSetAttribute(attn_mma,
        cudaFuncAttributeMaxDynamicSharedMemorySize, ATTN_SMEM);

    // pre-round x and weights to tf32
    round_pass<<<(RND_TOTAL4 + 255) / 256, 256>>>(x, Wq, Wk, Wv, Wo);

    // merged QKV projections (tf32 mma.sync)
    gemm_qkv<<<dim3(12, ROWS / 128), 256, GEMM_SMEM>>>(Qp, Kp, Vp);

    // gate + RoPE + RMS-norm
    postproc<<<ROWS, 256>>>(x, ve, cosb, sinb, Wg);

    // mma flash attention (M=128 tiles, 2 CTAs/SM, vectorized smem access)
    attn_mma<<<dim3(Tt / QT, HKV, Bb), 256, ATTN_SMEM>>>(win);

    // output projection
    gemm_tc<<<dim3(QDIM / 128, ROWS / 128), 256, GEMM_SMEM>>>(Yp, Wor, out, QDIM, Cc);
}

// round 15
// speedup vs baseline: 1.0647x; 1.0647x over previous
#include <cuda_runtime.h>
#include <cuda_bf16.h>
#include <math.h>
#include <cstdint>

// Problem constants
#define Bb 4
#define Tt 1024
#define Cc 1024
#define Hh 16
#define HKV 4
#define Dd 64
#define ROWS (Bb*Tt)          // 4096 tokens
#define QDIM (Hh*Dd)          // 1024
#define KVDIM (HKV*Dd)        // 256
#define GATE_CH 12

#define XN  (ROWS * Cc)
#define WQN (QDIM * Cc)
#define WKN (KVDIM * Cc)
#define WON (Cc * Cc)

// Scratch (no cudaMalloc allowed)
__device__ float g_Q[ROWS * QDIM];    // 16 MB
__device__ float g_K[ROWS * KVDIM];   // 4 MB
__device__ float g_V[ROWS * KVDIM];   // 4 MB
__device__ float g_Y[ROWS * QDIM];    // 16 MB
__device__ float g_Xr[XN];            // 16 MB  tf32-rounded x
__device__ float g_Wqr[WQN];          // 4 MB
__device__ float g_Wkr[WKN];          // 1 MB
__device__ float g_Wvr[WKN];          // 1 MB
__device__ float g_Wor[WON];          // 4 MB

__device__ __forceinline__ float tf32r(float x) {
    float y;
    asm("cvt.rna.tf32.f32 %0, %1;" : "=f"(y) : "f"(x));
    return y;
}

__device__ __forceinline__ void mma_tf32(float* d,
                                         const uint32_t* a, const uint32_t* b) {
    asm volatile(
        "mma.sync.aligned.m16n8k8.row.col.f32.tf32.tf32.f32 "
        "{%0,%1,%2,%3}, {%4,%5,%6,%7}, {%8,%9}, {%0,%1,%2,%3};"
        : "+f"(d[0]), "+f"(d[1]), "+f"(d[2]), "+f"(d[3])
        : "r"(a[0]), "r"(a[1]), "r"(a[2]), "r"(a[3]),
          "r"(b[0]), "r"(b[1]));
}

__device__ __forceinline__ void cpa16(float* s, const float* g) {
    uint32_t sa = (uint32_t)__cvta_generic_to_shared(s);
    asm volatile("cp.async.cg.shared.global [%0], [%1], 16;"
                 :: "r"(sa), "l"(g) : "memory");
}

// ---------------------------------------------------------------------------
// Pre-round pass: tf32-round x and all GEMM weights once (contiguous copies).
// ---------------------------------------------------------------------------
#define RND_TOTAL4 ((XN + WQN + 2 * WKN + WON) / 4)

__global__ __launch_bounds__(256) void round_pass(
    const float* __restrict__ x,
    const float* __restrict__ Wq, const float* __restrict__ Wk,
    const float* __restrict__ Wv, const float* __restrict__ Wo)
{
    int id = blockIdx.x * 256 + threadIdx.x;
    if (id >= RND_TOTAL4) return;
    int e = id * 4;
    const float* src;
    float* dst;
    if (e < XN)                { src = x  + e;         dst = g_Xr  + e; }
    else if ((e -= XN) < WQN)  { src = Wq + e;         dst = g_Wqr + e; }
    else if ((e -= WQN) < WKN) { src = Wk + e;         dst = g_Wkr + e; }
    else if ((e -= WKN) < WKN) { src = Wv + e;         dst = g_Wvr + e; }
    else                       { src = Wo + (e - WKN); dst = g_Wor + (e - WKN); }
    float4 v = *(const float4*)src;
    v.x = tf32r(v.x); v.y = tf32r(v.y); v.z = tf32r(v.z); v.w = tf32r(v.w);
    *(float4*)dst = v;
}

// ---------------------------------------------------------------------------
// tf32 mma.sync GEMM mainloop (R7 layout): acc = A[128,K] * B[128,K]^T
// ---------------------------------------------------------------------------
#define LDS_S 36
#define STG (128 * LDS_S)

__device__ __forceinline__ void gemm_main(
    const float* __restrict__ Ab, const float* __restrict__ Bp,
    int K, float* __restrict__ sm, float acc[2][8][4])
{
    float* smA = sm;
    float* smB = sm + 2 * STG;

    const int tid = threadIdx.x;
    const int wid = tid >> 5;
    const int lane = tid & 31;
    const int warp_m = wid & 3;
    const int warp_n = wid >> 2;
    const int group = lane >> 2;
    const int kq = lane & 3;

#pragma unroll
    for (int mt = 0; mt < 2; mt++)
#pragma unroll
        for (int nt = 0; nt < 8; nt++)
#pragma unroll
            for (int c = 0; c < 4; c++) acc[mt][nt][c] = 0.f;

    const int nk = K >> 5;

#pragma unroll
    for (int t = 0; t < 4; t++) {
        int idx = tid + t * 256;
        int row = idx >> 3;
        int c4  = (idx & 7) << 2;
        cpa16(smA + row * LDS_S + c4, Ab + (size_t)row * K + c4);
        cpa16(smB + row * LDS_S + c4, Bp + (size_t)row * K + c4);
    }
    asm volatile("cp.async.commit_group;" ::: "memory");

    for (int kc = 0; kc < nk; kc++) {
        asm volatile("cp.async.wait_group 0;" ::: "memory");
        __syncthreads();

        if (kc + 1 < nk) {
            float* dA = smA + ((kc + 1) & 1) * STG;
            float* dB = smB + ((kc + 1) & 1) * STG;
            const int koff = (kc + 1) << 5;
#pragma unroll
            for (int t = 0; t < 4; t++) {
                int idx = tid + t * 256;
                int row = idx >> 3;
                int c4  = (idx & 7) << 2;
                cpa16(dA + row * LDS_S + c4, Ab + (size_t)row * K + koff + c4);
                cpa16(dB + row * LDS_S + c4, Bp + (size_t)row * K + koff + c4);
            }
            asm volatile("cp.async.commit_group;" ::: "memory");
        }

        const uint32_t* As = (const uint32_t*)(smA + (kc & 1) * STG);
        const uint32_t* Bs = (const uint32_t*)(smB + (kc & 1) * STG);
#pragma unroll
        for (int ks = 0; ks < 4; ks++) {
            const int k0 = ks * 8;
            uint32_t af[2][4];
#pragma unroll
            for (int mt = 0; mt < 2; mt++) {
                const uint32_t* ar = As + (warp_m * 32 + mt * 16 + group) * LDS_S + k0 + kq;
                af[mt][0] = ar[0];
                af[mt][1] = ar[8 * LDS_S];
                af[mt][2] = ar[4];
                af[mt][3] = ar[8 * LDS_S + 4];
            }
            uint32_t bf[8][2];
#pragma unroll
            for (int nt = 0; nt < 8; nt++) {
                const uint32_t* br = Bs + (warp_n * 64 + nt * 8 + group) * LDS_S + k0 + kq;
                bf[nt][0] = br[0];
                bf[nt][1] = br[4];
            }
#pragma unroll
            for (int mt = 0; mt < 2; mt++)
#pragma unroll
                for (int nt = 0; nt < 8; nt++)
                    mma_tf32(acc[mt][nt], af[mt], bf[nt]);
        }
    }
}

// plain-store GEMM (final projection)
__global__ __launch_bounds__(256, 2) void gemm_tc(
    const float* __restrict__ A, const float* __restrict__ B,
    float* __restrict__ C, int N, int K)
{
    extern __shared__ float sm[];
    float acc[2][8][4];
    gemm_main(A + (size_t)blockIdx.y * 128 * K,
              B + (size_t)blockIdx.x * 128 * K, K, sm, acc);

    const int tid = threadIdx.x;
    const int wid = tid >> 5;
    const int lane = tid & 31;
    const int warp_m = wid & 3;
    const int warp_n = wid >> 2;
    const int group = lane >> 2;
    const int kq = lane & 3;
    float* Crow0 = C + (size_t)blockIdx.y * 128 * N + blockIdx.x * 128;
#pragma unroll
    for (int mt = 0; mt < 2; mt++) {
        int r = warp_m * 32 + mt * 16 + group;
#pragma unroll
        for (int nt = 0; nt < 8; nt++) {
            int cn = warp_n * 64 + nt * 8 + 2 * kq;
            *(float2*)(Crow0 + (size_t)r * N + cn) =
                make_float2(acc[mt][nt][0], acc[mt][nt][1]);
            *(float2*)(Crow0 + (size_t)(r + 8) * N + cn) =
                make_float2(acc[mt][nt][2], acc[mt][nt][3]);
        }
    }
}

// ---------------------------------------------------------------------------
// Fused QKV projection + postproc.
// grid.x 0..7 -> Q (RoPE+RMS), 8..9 -> K (RoPE+RMS), 10..11 -> V (gate+ve).
// Each warp's 64-col slice is one complete head; RoPE pairs (d, d+32) are
// held by the same thread (nt and nt+4, same component).
// ---------------------------------------------------------------------------
__global__ __launch_bounds__(256, 2) void gemm_qkv(
    const float* __restrict__ x, const float* __restrict__ ve,
    const float* __restrict__ cosb, const float* __restrict__ sinb,
    const float* __restrict__ Wg,
    float* __restrict__ Qo, float* __restrict__ Ko, float* __restrict__ Vo)
{
    extern __shared__ float sm[];
    const int bx = blockIdx.x;
    const float* Bp;
    float* Cp;
    int N, nb;
    bool isV = false, isQ = false;
    if (bx < 8)       { Bp = g_Wqr; Cp = Qo; N = QDIM;  nb = bx;      isQ = true; }
    else if (bx < 10) { Bp = g_Wkr; Cp = Ko; N = KVDIM; nb = bx - 8; }
    else              { Bp = g_Wvr; Cp = Vo; N = KVDIM; nb = bx - 10; isV = true; }

    const int tok0 = blockIdx.y * 128;

    float acc[2][8][4];
    gemm_main(g_Xr + (size_t)tok0 * Cc, Bp + (size_t)nb * 128 * Cc, Cc, sm, acc);

    const int tid = threadIdx.x;
    const int wid = tid >> 5;
    const int lane = tid & 31;
    const int warp_m = wid & 3;
    const int warp_n = wid >> 2;
    const int group = lane >> 2;
    const int kq = lane & 3;

    float* Crow0 = Cp + (size_t)tok0 * N + nb * 128;

    if (!isV) {
        // --- RoPE + RMS-norm on Q/K tiles ---
#pragma unroll
        for (int mt = 0; mt < 2; mt++) {
#pragma unroll
            for (int half = 0; half < 2; half++) {
                const int rl = warp_m * 32 + mt * 16 + group + half * 8;
                const int t = (tok0 + rl) & (Tt - 1);
                const int i0 = half * 2;
                float ss = 0.f;
#pragma unroll
                for (int nt = 0; nt < 4; nt++) {
                    const int d = nt * 8 + 2 * kq;
                    float2 cv = *(const float2*)&cosb[t * 32 + d];
                    float2 sv = *(const float2*)&sinb[t * 32 + d];
                    float x1a = acc[mt][nt][i0],     x1b = acc[mt][nt][i0 + 1];
                    float x2a = acc[mt][nt + 4][i0], x2b = acc[mt][nt + 4][i0 + 1];
                    float y1a = x1a * cv.x + x2a * sv.x;
                    float y1b = x1b * cv.y + x2b * sv.y;
                    float y2a = x2a * cv.x - x1a * sv.x;
                    float y2b = x2b * cv.y - x1b * sv.y;
                    acc[mt][nt][i0] = y1a;     acc[mt][nt][i0 + 1] = y1b;
                    acc[mt][nt + 4][i0] = y2a; acc[mt][nt + 4][i0 + 1] = y2b;
                    ss += y1a * y1a + y1b * y1b + y2a * y2a + y2b * y2b;
                }
                ss += __shfl_xor_sync(0xffffffffu, ss, 1);
                ss += __shfl_xor_sync(0xffffffffu, ss, 2);
                float sc = 1.2f * rsqrtf(ss * (1.0f / Dd) + 1.1920929e-7f);
#pragma unroll
                for (int nt = 0; nt < 8; nt++) {
                    acc[mt][nt][i0]     *= sc;
                    acc[mt][nt][i0 + 1] *= sc;
                }
            }
        }
    } else {
        // --- V gating: gate_s[row][head] for the tile's 2 kv-heads ---
        __syncthreads();                  // done with mainloop smem
        float* gate_s = sm;               // 256 floats
        {
            int row = tid >> 1;
            int hd = tid & 1;
            const float* xr = x + (size_t)(tok0 + row) * Cc;
            const float* wg = Wg + (2 * nb + hd) * GATE_CH;
            float p = 0.f;
#pragma unroll
            for (int j = 0; j < GATE_CH; j++)
                p += xr[j] * wg[j];
            gate_s[row * 2 + hd] = 3.f / (1.f + __expf(-p));
        }
        __syncthreads();
        const int headg = 2 * nb + warp_n;
#pragma unroll
        for (int mt = 0; mt < 2; mt++) {
#pragma unroll
            for (int half = 0; half < 2; half++) {
                const int rl = warp_m * 32 + mt * 16 + group + half * 8;
                const float gate = gate_s[rl * 2 + warp_n];
                const int i0 = half * 2;
                const float* ver = ve + (size_t)(tok0 + rl) * KVDIM + headg * 64;
#pragma unroll
                for (int nt = 0; nt < 8; nt++) {
                    const int cl = nt * 8 + 2 * kq;
                    float2 vv = *(const float2*)&ver[cl];
                    acc[mt][nt][i0]     = fmaf(gate, vv.x, acc[mt][nt][i0]);
                    acc[mt][nt][i0 + 1] = fmaf(gate, vv.y, acc[mt][nt][i0 + 1]);
                }
            }
        }
    }

    // store
#pragma unroll
    for (int mt = 0; mt < 2; mt++) {
        int r = warp_m * 32 + mt * 16 + group;
#pragma unroll
        for (int nt = 0; nt < 8; nt++) {
            int cn = warp_n * 64 + nt * 8 + 2 * kq;
            *(float2*)(Crow0 + (size_t)r * N + cn) =
                make_float2(acc[mt][nt][0], acc[mt][nt][1]);
            *(float2*)(Crow0 + (size_t)(r + 8) * N + cn) =
                make_float2(acc[mt][nt][2], acc[mt][nt][3]);
        }
    }
}

// ---------------------------------------------------------------------------
// mma.sync flash attention (R7 version). CTA = (qtile64, kv-head g, batch b),
// covering all 4 GQA q-heads: M=256 score rows. Epilogue stores tf32-rounded Y.
// ---------------------------------------------------------------------------
#define SST 68   // smem row stride (floats)

__global__ __launch_bounds__(256, 1) void attn_mma(const int* __restrict__ wptr)
{
    extern __shared__ float dsm[];
    float* Ss = dsm;                        // [256][SST]
    float* Ks = dsm + 256 * SST;            // [64][SST]
    float* Vs = Ks + 64 * SST;              // [64][SST]

    const int qt = blockIdx.x, g = blockIdx.y, b = blockIdx.z;
    const int tid = threadIdx.x;
    const int wid = tid >> 5;
    const int lane = tid & 31;
    const int group = lane >> 2;
    const int kq = lane & 3;
    const int rbase = wid * 32;
    const int head = g * 4 + (wid >> 1);
    const int q0 = qt * 64;
    const int qloc0 = (wid & 1) * 32;

    uint32_t qf[2][8][4];
    {
        const float* Qb = g_Q + ((size_t)(b * Tt + q0)) * QDIM + head * Dd;
#pragma unroll
        for (int mt = 0; mt < 2; mt++) {
            int r0 = qloc0 + mt * 16 + group;
#pragma unroll
            for (int ks = 0; ks < 8; ks++) {
                int k0 = ks * 8 + kq;
                qf[mt][ks][0] = __float_as_uint(tf32r(Qb[(size_t)r0 * QDIM + k0]));
                qf[mt][ks][1] = __float_as_uint(tf32r(Qb[(size_t)(r0 + 8) * QDIM + k0]));
                qf[mt][ks][2] = __float_as_uint(tf32r(Qb[(size_t)r0 * QDIM + k0 + 4]));
                qf[mt][ks][3] = __float_as_uint(tf32r(Qb[(size_t)(r0 + 8) * QDIM + k0 + 4]));
            }
        }
    }

    float oacc[2][8][4];
#pragma unroll
    for (int mt = 0; mt < 2; mt++)
#pragma unroll
        for (int nt = 0; nt < 8; nt++)
#pragma unroll
            for (int c = 0; c < 4; c++) oacc[mt][nt][c] = 0.f;

    float mrow[2][2] = {{-1e30f, -1e30f}, {-1e30f, -1e30f}};
    float lrow[2][2] = {{0.f, 0.f}, {0.f, 0.f}};

    const int w = wptr[0];
    int jmin = q0 - w; if (jmin < 0) jmin = 0;

    for (int c0 = (jmin >> 6) << 6; c0 <= q0; c0 += 64) {
#pragma unroll
        for (int t = 0; t < 4; t++) {
            int idx = tid + t * 256;
            int key = idx >> 4;
            int d4  = (idx & 15) << 2;
            size_t src = ((size_t)(b * Tt + c0 + key)) * KVDIM + g * Dd + d4;
            float4 kv = *(const float4*)&g_K[src];
            float4 vv = *(const float4*)&g_V[src];
            float* kd = &Ks[key * SST + d4];
            kd[0] = tf32r(kv.x); kd[1] = tf32r(kv.y);
            kd[2] = tf32r(kv.z); kd[3] = tf32r(kv.w);
            float* vd = &Vs[key * SST + d4];
            vd[0] = tf32r(vv.x); vd[1] = tf32r(vv.y);
            vd[2] = tf32r(vv.z); vd[3] = tf32r(vv.w);
        }
        __syncthreads();

        float sacc[2][8][4];
#pragma unroll
        for (int mt = 0; mt < 2; mt++)
#pragma unroll
            for (int nt = 0; nt < 8; nt++)
#pragma unroll
                for (int c = 0; c < 4; c++) sacc[mt][nt][c] = 0.f;

#pragma unroll
        for (int ks = 0; ks < 8; ks++) {
            const int k0 = ks * 8;
            uint32_t bf[8][2];
#pragma unroll
            for (int nt = 0; nt < 8; nt++) {
                bf[nt][0] = __float_as_uint(Ks[(nt * 8 + group) * SST + k0 + kq]);
                bf[nt][1] = __float_as_uint(Ks[(nt * 8 + group) * SST + k0 + kq + 4]);
            }
#pragma unroll
            for (int mt = 0; mt < 2; mt++)
#pragma unroll
                for (int nt = 0; nt < 8; nt++)
                    mma_tf32(sacc[mt][nt], qf[mt][ks], bf[nt]);
        }

#pragma unroll
        for (int mt = 0; mt < 2; mt++) {
            const int i0 = q0 + qloc0 + mt * 16 + group;
            const int i1 = i0 + 8;
            float cmax0 = -1e30f, cmax1 = -1e30f;
#pragma unroll
            for (int nt = 0; nt < 8; nt++) {
                int jg = c0 + nt * 8 + 2 * kq;
                float s;
                s = (jg     <= i0 && (i0 - jg)     <= w) ? sacc[mt][nt][0] * 0.125f : -1e30f;
                sacc[mt][nt][0] = s; cmax0 = fmaxf(cmax0, s);
                s = (jg + 1 <= i0 && (i0 - jg - 1) <= w) ? sacc[mt][nt][1] * 0.125f : -1e30f;
                sacc[mt][nt][1] = s; cmax0 = fmaxf(cmax0, s);
                s = (jg     <= i1 && (i1 - jg)     <= w) ? sacc[mt][nt][2] * 0.125f : -1e30f;
                sacc[mt][nt][2] = s; cmax1 = fmaxf(cmax1, s);
                s = (jg + 1 <= i1 && (i1 - jg - 1) <= w) ? sacc[mt][nt][3] * 0.125f : -1e30f;
                sacc[mt][nt][3] = s; cmax1 = fmaxf(cmax1, s);
            }
            cmax0 = fmaxf(cmax0, __shfl_xor_sync(0xffffffffu, cmax0, 1));
            cmax0 = fmaxf(cmax0, __shfl_xor_sync(0xffffffffu, cmax0, 2));
            cmax1 = fmaxf(cmax1, __shfl_xor_sync(0xffffffffu, cmax1, 1));
            cmax1 = fmaxf(cmax1, __shfl_xor_sync(0xffffffffu, cmax1, 2));

            float mn0 = fmaxf(mrow[mt][0], cmax0);
            float mn1 = fmaxf(mrow[mt][1], cmax1);
            float r0 = __expf(mrow[mt][0] - mn0);
            float r1 = __expf(mrow[mt][1] - mn1);
            mrow[mt][0] = mn0; mrow[mt][1] = mn1;
            lrow[mt][0] *= r0; lrow[mt][1] *= r1;
#pragma unroll
            for (int nt = 0; nt < 8; nt++) {
                oacc[mt][nt][0] *= r0; oacc[mt][nt][1] *= r0;
                oacc[mt][nt][2] *= r1; oacc[mt][nt][3] *= r1;
            }
            const int prow0 = rbase + mt * 16 + group;
#pragma unroll
            for (int nt = 0; nt < 8; nt++) {
                float p0 = tf32r(__expf(sacc[mt][nt][0] - mn0));
                float p1 = tf32r(__expf(sacc[mt][nt][1] - mn0));
                float p2 = tf32r(__expf(sacc[mt][nt][2] - mn1));
                float p3 = tf32r(__expf(sacc[mt][nt][3] - mn1));
                lrow[mt][0] += p0 + p1;
                lrow[mt][1] += p2 + p3;
                *(float2*)&Ss[prow0 * SST + nt * 8 + 2 * kq] = make_float2(p0, p1);
                *(float2*)&Ss[(prow0 + 8) * SST + nt * 8 + 2 * kq] = make_float2(p2, p3);
            }
        }
        __syncwarp();

#pragma unroll
        for (int ks = 0; ks < 8; ks++) {
            const int k0 = ks * 8;
            uint32_t vf[8][2];
#pragma unroll
            for (int nt = 0; nt < 8; nt++) {
                vf[nt][0] = __float_as_uint(Vs[(k0 + kq) * SST + nt * 8 + group]);
                vf[nt][1] = __float_as_uint(Vs[(k0 + kq + 4) * SST + nt * 8 + group]);
            }
            uint32_t af[2][4];
#pragma unroll
            for (int mt = 0; mt < 2; mt++) {
                const int pr = rbase + mt * 16 + group;
                af[mt][0] = __float_as_uint(Ss[pr * SST + k0 + kq]);
                af[mt][1] = __float_as_uint(Ss[(pr + 8) * SST + k0 + kq]);
                af[mt][2] = __float_as_uint(Ss[pr * SST + k0 + kq + 4]);
                af[mt][3] = __float_as_uint(Ss[(pr + 8) * SST + k0 + kq + 4]);
            }
#pragma unroll
            for (int mt = 0; mt < 2; mt++)
#pragma unroll
                for (int nt = 0; nt < 8; nt++)
                    mma_tf32(oacc[mt][nt], af[mt], vf[nt]);
        }
        __syncthreads();
    }

#pragma unroll
    for (int mt = 0; mt < 2; mt++) {
        float l0 = lrow[mt][0], l1 = lrow[mt][1];
        l0 += __shfl_xor_sync(0xffffffffu, l0, 1);
        l0 += __shfl_xor_sync(0xffffffffu, l0, 2);
        l1 += __shfl_xor_sync(0xffffffffu, l1, 1);
        l1 += __shfl_xor_sync(0xffffffffu, l1, 2);
        float inv0 = 1.f / l0, inv1 = 1.f / l1;
        int r0 = q0 + qloc0 + mt * 16 + group;
        float* Y0 = g_Y + ((size_t)(b * Tt + r0)) * QDIM + head * Dd;
        float* Y1 = g_Y + ((size_t)(b * Tt + r0 + 8)) * QDIM + head * Dd;
#pragma unroll
        for (int nt = 0; nt < 8; nt++) {
            int cn = nt * 8 + 2 * kq;
            *(float2*)(Y0 + cn) = make_float2(tf32r(oacc[mt][nt][0] * inv0),
                                              tf32r(oacc[mt][nt][1] * inv0));
            *(float2*)(Y1 + cn) = make_float2(tf32r(oacc[mt][nt][2] * inv1),
                                              tf32r(oacc[mt][nt][3] * inv1));
        }
    }
}

// ---------------------------------------------------------------------------
extern "C" void kernel_launch(void* const* d_in, const int* in_sizes, int n_in,
                              void* d_out, int out_size)
{
    const float* x    = (const float*)d_in[0];
    const float* ve   = (const float*)d_in[1];
    const float* cosb = (const float*)d_in[2];
    const float* sinb = (const float*)d_in[3];
    const float* Wq   = (const float*)d_in[4];
    const float* Wk   = (const float*)d_in[5];
    const float* Wv   = (const float*)d_in[6];
    const float* Wo   = (const float*)d_in[7];
    const float* Wg   = (const float*)d_in[8];
    const int*   win  = (const int*)d_in[9];

    float* out = (float*)d_out;

    float* Qp; cudaGetSymbolAddress((void**)&Qp, g_Q);
    float* Kp; cudaGetSymbolAddress((void**)&Kp, g_K);
    float* Vp; cudaGetSymbolAddress((void**)&Vp, g_V);
    float* Yp; cudaGetSymbolAddress((void**)&Yp, g_Y);
    float* Wor; cudaGetSymbolAddress((void**)&Wor, g_Wor);

    const int GEMM_SMEM = 4 * STG * 4;            // 73728 bytes
    const int ATTN_SMEM = (256 + 128) * SST * 4;  // 104448 bytes
    cudaFuncSetAttribute(gemm_qkv,
        cudaFuncAttributeMaxDynamicSharedMemorySize, GEMM_SMEM);
    cudaFuncSetAttribute(gemm_tc,
        cudaFuncAttributeMaxDynamicSharedMemorySize, GEMM_SMEM);
    cudaFuncSetAttribute(attn_mma,
        cudaFuncAttributeMaxDynamicSharedMemorySize, ATTN_SMEM);

    // pre-round x and weights to tf32
    round_pass<<<(RND_TOTAL4 + 255) / 256, 256>>>(x, Wq, Wk, Wv, Wo);

    // fused QKV projections + gate + RoPE + RMS-norm
    gemm_qkv<<<dim3(12, ROWS / 128), 256, GEMM_SMEM>>>(
        x, ve, cosb, sinb, Wg, Qp, Kp, Vp);

    // mma flash attention (M=256, R7 config)
    attn_mma<<<dim3(Tt / 64, HKV, Bb), 256, ATTN_SMEM>>>(win);

    // output projection
    gemm_tc<<<dim3(QDIM / 128, ROWS / 128), 256, GEMM_SMEM>>>(Yp, Wor, out, QDIM, Cc);
}